// round 9
// baseline (speedup 1.0000x reference)
#include <cuda_runtime.h>
#include <cuda_fp16.h>

#define NN 100000
#define EE 3200000
#define NBLK ((NN + 1023) / 1024)   // 98 scan blocks (all co-resident)

// ---- scratch (device globals; no allocation allowed) ----
__device__ int    g_cnt[NN];
__device__ int    g_blocksum[NBLK];    // published totals+1 (memset 0 per replay)
__device__ int    g_rowptr[NN + 1];
__device__ int    g_cur[NN];
__device__ int    g_csr_src[EE];
__device__ float  g_dis[NN];           // rsqrt(deg)
__device__ __half g_hx[NN * 16];       // x~ block input (dis-scaled fp16)
__device__ __half g_hy[NN * 16];       // y  = agg16 out (fp16)
__device__ __half g_h1[NN * 32];       // z~ = gemm_fused out (dis-scaled fp16)
__device__ __half g_hz[NN * 32];       // z  = agg32 out (fp16)
__device__ __half g_h2[NN * 16];       // h~ = gemm3 out (dis-scaled fp16)

// ---------------- CSR build ----------------
__global__ void k_hist(const int* __restrict__ dst) {
    int e = blockIdx.x * blockDim.x + threadIdx.x;
    if (e < EE) atomicAdd(&g_cnt[dst[e]], 1);
}

// Fused scan + finalize + prescale. 98 blocks x 1024 threads, all co-resident:
// each block scans its 1024 counts, publishes total+1, spins for all totals,
// then finalizes rowptr/cur/dis and prescales x -> g_hx.
__global__ void __launch_bounds__(1024, 1) k_scanfin(const float* __restrict__ x) {
    __shared__ int sh[1024];
    __shared__ int bs[NBLK];
    int tid = threadIdx.x;
    int b = blockIdx.x;
    int i = b * 1024 + tid;
    int c = (i < NN) ? g_cnt[i] : 0;
    sh[tid] = c;
    __syncthreads();
#pragma unroll
    for (int off = 1; off < 1024; off <<= 1) {
        int t = (tid >= off) ? sh[tid - off] : 0;
        __syncthreads();
        sh[tid] += t;
        __syncthreads();
    }
    int excl = sh[tid] - c;

    // publish this block's total (+1 so 0 means "not ready")
    if (tid == 0) {
        ((volatile int*)g_blocksum)[b] = sh[1023] + 1;
        __threadfence();
    }
    // spin until every block's total is published
    if (tid < NBLK) {
        volatile int* vb = (volatile int*)g_blocksum;
        int v;
        do { v = vb[tid]; } while (v == 0);
        bs[tid] = v - 1;
    }
    __syncthreads();
    // exclusive prefix over the 98 totals (single warp)
    if (tid < 32) {
        int lane = tid;
        int acc = 0;
        for (int base = 0; base < NBLK; base += 32) {
            int j = base + lane;
            int orig = (j < NBLK) ? bs[j] : 0;
            int v = orig;
#pragma unroll
            for (int off = 1; off < 32; off <<= 1) {
                int t = __shfl_up_sync(0xffffffffu, v, off);
                if (lane >= off) v += t;
            }
            int ex = acc + v - orig;
            acc += __shfl_sync(0xffffffffu, v, 31);
            __syncwarp();
            if (j < NBLK) bs[j] = ex;
        }
    }
    __syncthreads();

    if (i >= NN) return;
    int r = excl + bs[b];
    g_rowptr[i] = r;
    g_cur[i] = r;
    float d = rsqrtf((float)c + 1.0f);
    g_dis[i] = d;
    if (i == 0) g_rowptr[NN] = EE;
    __half2* o = ((__half2*)g_hx) + i * 8;
#pragma unroll
    for (int j = 0; j < 8; j++) {
        float a = x[i * 16 + 2 * j] * d;
        float bb = x[i * 16 + 2 * j + 1] * d;
        o[j] = __floats2half2_rn(a, bb);
    }
}

__global__ void k_scatter(const int* __restrict__ src, const int* __restrict__ dst) {
    int e = blockIdx.x * blockDim.x + threadIdx.x;
    if (e >= EE) return;
    int pos = atomicAdd(&g_cur[dst[e]], 1);
    g_csr_src[pos] = src[e];
}

// ---------------- aggregation ----------------
// D=16 fp16 rows (32B). 8 lanes/row x half2, 8 independent row-LDGs per iter
// -> 32 edges in flight, avg 1 iteration per warp (deg~32).
// MODE 0: y fp16 | MODE 1: softmax -> fp16 dis-scaled | MODE 2: softmax -> fp32
template <int MODE>
__global__ void k_agg16h(const __half* __restrict__ xin, void* __restrict__ yout,
                         const float* __restrict__ bsm) {
    int warp = (blockIdx.x * blockDim.x + threadIdx.x) >> 5;
    if (warp >= NN) return;
    int lane = threadIdx.x & 31;
    int r = lane & 7;            // feature pair
    int g = lane >> 3;           // edge slot 0..3
    int beg = __ldg(&g_rowptr[warp]);
    int end = __ldg(&g_rowptr[warp + 1]);
    const __half2* __restrict__ x2 = (const __half2*)xin;

    float ax = 0.f, ay = 0.f;
    if (g == 0) {
        float2 f = __half22float2(x2[warp * 8 + r]);
        ax = f.x; ay = f.y;
    }
    for (int e = beg + g; e < end; e += 32) {
        int idx[8]; bool vv[8];
#pragma unroll
        for (int u = 0; u < 8; u++) {
            int eu = e + 4 * u;
            vv[u] = eu < end;
            idx[u] = vv[u] ? __ldg(&g_csr_src[eu]) : 0;
        }
        __half2 row[8];
#pragma unroll
        for (int u = 0; u < 8; u++) row[u] = x2[idx[u] * 8 + r];
#pragma unroll
        for (int u = 0; u < 8; u++)
            if (vv[u]) { float2 f = __half22float2(row[u]); ax += f.x; ay += f.y; }
    }
    ax += __shfl_xor_sync(0xffffffffu, ax, 8);
    ay += __shfl_xor_sync(0xffffffffu, ay, 8);
    ax += __shfl_xor_sync(0xffffffffu, ax, 16);
    ay += __shfl_xor_sync(0xffffffffu, ay, 16);

    float d = g_dis[warp];
    ax *= d; ay *= d;

    if (MODE == 0) {
        if (lane < 8) ((__half2*)yout)[warp * 8 + r] = __floats2half2_rn(ax, ay);
        return;
    }
    ax += bsm[2 * r]; ay += bsm[2 * r + 1];
    float m = fmaxf(ax, ay);
    m = fmaxf(m, __shfl_xor_sync(0xffffffffu, m, 1));
    m = fmaxf(m, __shfl_xor_sync(0xffffffffu, m, 2));
    m = fmaxf(m, __shfl_xor_sync(0xffffffffu, m, 4));
    ax = __expf(ax - m); ay = __expf(ay - m);
    float s = ax + ay;
    s += __shfl_xor_sync(0xffffffffu, s, 1);
    s += __shfl_xor_sync(0xffffffffu, s, 2);
    s += __shfl_xor_sync(0xffffffffu, s, 4);
    float inv = 1.0f / s;
    ax *= inv; ay *= inv;

    if (MODE == 1) {
        if (lane < 8) ((__half2*)yout)[warp * 8 + r] = __floats2half2_rn(ax * d, ay * d);
    } else {
        if (lane < 8) ((float2*)yout)[warp * 8 + r] = make_float2(ax, ay);
    }
}

// D=32 fp16 rows (64B). 16 lanes/row x half2, 8 independent LDGs per iter
// -> 16 edges in flight, avg 2 iterations (deg~32).
__global__ void k_agg32h(const __half* __restrict__ xin, __half* __restrict__ yout) {
    int warp = (blockIdx.x * blockDim.x + threadIdx.x) >> 5;
    if (warp >= NN) return;
    int lane = threadIdx.x & 31;
    int r = lane & 15;           // feature pair
    int g = lane >> 4;           // edge slot 0..1
    int beg = __ldg(&g_rowptr[warp]);
    int end = __ldg(&g_rowptr[warp + 1]);
    const __half2* __restrict__ x2 = (const __half2*)xin;

    float ax = 0.f, ay = 0.f;
    if (g == 0) {
        float2 f = __half22float2(x2[warp * 16 + r]);
        ax = f.x; ay = f.y;
    }
    for (int e = beg + g; e < end; e += 16) {
        int idx[8]; bool vv[8];
#pragma unroll
        for (int u = 0; u < 8; u++) {
            int eu = e + 2 * u;
            vv[u] = eu < end;
            idx[u] = vv[u] ? __ldg(&g_csr_src[eu]) : 0;
        }
        __half2 row[8];
#pragma unroll
        for (int u = 0; u < 8; u++) row[u] = x2[idx[u] * 16 + r];
#pragma unroll
        for (int u = 0; u < 8; u++)
            if (vv[u]) { float2 f = __half22float2(row[u]); ax += f.x; ay += f.y; }
    }
    ax += __shfl_xor_sync(0xffffffffu, ax, 16);
    ay += __shfl_xor_sync(0xffffffffu, ay, 16);

    float d = g_dis[warp];
    if (lane < 16)
        ((__half2*)yout)[warp * 16 + r] = __floats2half2_rn(ax * d, ay * d);
}

// ---------------- fused per-node GEMM: z~ = dis * (relu(y@W1 + b1) @ W2) ----------------
// W1 transposed in smem to [k][m] so both weight streams are float4 LDS.
__global__ void k_gemm_fused(const __half* __restrict__ yin, __half* __restrict__ zout,
                             const float* __restrict__ W1, const float* __restrict__ b1,
                             const float* __restrict__ W2) {
    __shared__ float W1t[64 * 16];   // [k][m]
    __shared__ float W2s[64 * 32];   // [k][j]
    __shared__ float b1s[64];
    for (int t = threadIdx.x; t < 16 * 64; t += blockDim.x) {
        int m = t >> 6, k = t & 63;          // W1 is [m][k]
        W1t[k * 16 + m] = W1[t];
    }
    for (int t = threadIdx.x; t < 64 * 32; t += blockDim.x) W2s[t] = W2[t];
    for (int t = threadIdx.x; t < 64; t += blockDim.x) b1s[t] = b1[t];
    __syncthreads();

    int i = blockIdx.x * blockDim.x + threadIdx.x;
    if (i >= NN) return;

    float xr[16];
    {
        const uint4* yv = (const uint4*)yin;
        uint4 q0 = yv[i * 2 + 0];
        uint4 q1 = yv[i * 2 + 1];
        const unsigned* w0 = (const unsigned*)&q0;
        const unsigned* w1 = (const unsigned*)&q1;
#pragma unroll
        for (int j = 0; j < 4; j++) {
            float2 f = __half22float2(*reinterpret_cast<const __half2*>(&w0[j]));
            xr[2 * j] = f.x; xr[2 * j + 1] = f.y;
            float2 g2 = __half22float2(*reinterpret_cast<const __half2*>(&w1[j]));
            xr[8 + 2 * j] = g2.x; xr[8 + 2 * j + 1] = g2.y;
        }
    }
    float4 z4[8];
#pragma unroll
    for (int j = 0; j < 8; j++) z4[j] = make_float4(0.f, 0.f, 0.f, 0.f);

    const float4* W1t4 = (const float4*)W1t;
    const float4* W2s4 = (const float4*)W2s;
#pragma unroll 4
    for (int k = 0; k < 64; k++) {
        float t = b1s[k];
#pragma unroll
        for (int q = 0; q < 4; q++) {
            float4 w = W1t4[k * 4 + q];
            t += xr[4 * q + 0] * w.x + xr[4 * q + 1] * w.y
               + xr[4 * q + 2] * w.z + xr[4 * q + 3] * w.w;
        }
        t = fmaxf(t, 0.0f);
#pragma unroll
        for (int j = 0; j < 8; j++) {
            float4 w = W2s4[k * 8 + j];
            z4[j].x += t * w.x; z4[j].y += t * w.y;
            z4[j].z += t * w.z; z4[j].w += t * w.w;
        }
    }

    float d = g_dis[i];
    __half2* o = ((__half2*)zout) + i * 16;
#pragma unroll
    for (int j = 0; j < 8; j++) {
        o[2 * j + 0] = __floats2half2_rn(z4[j].x * d, z4[j].y * d);
        o[2 * j + 1] = __floats2half2_rn(z4[j].z * d, z4[j].w * d);
    }
}

// ---------------- gemm3: h~ = dis * (relu(z + b2) @ W3) ----------------
__global__ void k_gemm3(const __half* __restrict__ zin, __half* __restrict__ hout,
                        const float* __restrict__ b2, const float* __restrict__ W3) {
    __shared__ float W3s[32 * 16];   // [k][j], j consecutive
    __shared__ float b2s[32];
    for (int t = threadIdx.x; t < 32 * 16; t += blockDim.x) W3s[t] = W3[t];
    for (int t = threadIdx.x; t < 32; t += blockDim.x) b2s[t] = b2[t];
    __syncthreads();

    int i = blockIdx.x * blockDim.x + threadIdx.x;
    if (i >= NN) return;

    float4 acc[4];
#pragma unroll
    for (int j = 0; j < 4; j++) acc[j] = make_float4(0.f, 0.f, 0.f, 0.f);

    const float4* W3s4 = (const float4*)W3s;
    const uint4* zv = (const uint4*)zin;
#pragma unroll
    for (int m = 0; m < 4; m++) {
        uint4 q = zv[i * 4 + m];
        const unsigned* w = (const unsigned*)&q;
#pragma unroll
        for (int p = 0; p < 4; p++) {
            float2 f = __half22float2(*reinterpret_cast<const __half2*>(&w[p]));
            int k0 = m * 8 + 2 * p;
            float t0 = fmaxf(f.x + b2s[k0], 0.0f);
            float t1 = fmaxf(f.y + b2s[k0 + 1], 0.0f);
#pragma unroll
            for (int j = 0; j < 4; j++) {
                float4 wa = W3s4[k0 * 4 + j];
                float4 wb = W3s4[(k0 + 1) * 4 + j];
                acc[j].x += t0 * wa.x + t1 * wb.x;
                acc[j].y += t0 * wa.y + t1 * wb.y;
                acc[j].z += t0 * wa.z + t1 * wb.z;
                acc[j].w += t0 * wa.w + t1 * wb.w;
            }
        }
    }

    float d = g_dis[i];
    __half2* o = ((__half2*)hout) + i * 8;
#pragma unroll
    for (int j = 0; j < 4; j++) {
        o[2 * j + 0] = __floats2half2_rn(acc[j].x * d, acc[j].y * d);
        o[2 * j + 1] = __floats2half2_rn(acc[j].z * d, acc[j].w * d);
    }
}

// ---------------- launch ----------------
extern "C" void kernel_launch(void* const* d_in, const int* in_sizes, int n_in,
                              void* d_out, int out_size) {
    const float* x  = (const float*)d_in[0];
    const int*   ei = (const int*)d_in[1];
    const int*   src = ei;
    const int*   dst = ei + EE;
    const float* W1 = (const float*)d_in[2];
    const float* b1 = (const float*)d_in[3];
    const float* W2 = (const float*)d_in[4];
    const float* b2 = (const float*)d_in[5];
    const float* W3 = (const float*)d_in[6];
    const float* b3 = (const float*)d_in[7];
    float* out = (float*)d_out;

    __half *pHX, *pHY, *pH1, *pHZ, *pH2;
    int *pCnt, *pBS;
    cudaGetSymbolAddress((void**)&pHX, g_hx);
    cudaGetSymbolAddress((void**)&pHY, g_hy);
    cudaGetSymbolAddress((void**)&pH1, g_h1);
    cudaGetSymbolAddress((void**)&pHZ, g_hz);
    cudaGetSymbolAddress((void**)&pH2, g_h2);
    cudaGetSymbolAddress((void**)&pCnt, g_cnt);
    cudaGetSymbolAddress((void**)&pBS, g_blocksum);

    const int TB = 256;
    const int gE = (EE + TB - 1) / TB;
    const int gW = (NN * 32 + TB - 1) / TB;   // warp-per-node
    const int gG = (NN + 127) / 128;

    // CSR build (kernels: hist=1, scanfin=2, scatter=3 -> first agg16 is 4th
    // kernel = the one ncu captures)
    cudaMemsetAsync(pCnt, 0, NN * sizeof(int));
    cudaMemsetAsync(pBS, 0, NBLK * sizeof(int));
    k_hist<<<gE, TB>>>(dst);
    k_scanfin<<<NBLK, 1024>>>(x);
    k_scatter<<<gE, TB>>>(src, dst);

    for (int blk = 0; blk < 5; blk++) {
        k_agg16h<0><<<gW, TB>>>(pHX, pHY, nullptr);
        k_gemm_fused<<<gG, 128>>>(pHY, pH1, W1 + blk * 16 * 64, b1 + blk * 64,
                                  W2 + blk * 64 * 32);
        k_agg32h<<<gW, TB>>>(pH1, pHZ);
        k_gemm3<<<gG, 128>>>(pHZ, pH2, b2 + blk * 32, W3 + blk * 32 * 16);
        if (blk == 4)
            k_agg16h<2><<<gW, TB>>>(pH2, out, b3 + blk * 16);
        else
            k_agg16h<1><<<gW, TB>>>(pH2, pHX, b3 + blk * 16);
    }
}

// round 10
// speedup vs baseline: 1.0915x; 1.0915x over previous
#include <cuda_runtime.h>
#include <cuda_fp16.h>

#define NN 100000
#define EE 3200000
#define NBLK ((NN + 1023) / 1024)   // 98 scan blocks (all co-resident)

// ---- scratch (device globals; no allocation allowed) ----
__device__ int    g_cnt[NN];
__device__ int    g_blocksum[NBLK];    // published totals+1 (memset 0 per replay)
__device__ int    g_rowptr[NN + 1];
__device__ int    g_cur[NN];
__device__ int    g_csr_src[EE];
__device__ float  g_dis[NN];            // rsqrt(deg)
// gathered arrays have a dummy zero row at index NN
__device__ __half g_hx[(NN + 1) * 16];  // x~ block input (dis-scaled fp16)
__device__ __half g_hy[NN * 16];        // y  = agg16 out (fp16)
__device__ __half g_h1[(NN + 1) * 32];  // z~ = gemm_fused out (dis-scaled fp16)
__device__ __half g_hz[NN * 32];        // z  = agg32 out (fp16)
__device__ __half g_h2[(NN + 1) * 16];  // h~ = gemm3 out (dis-scaled fp16)

// ---------------- CSR build ----------------
__global__ void k_hist(const int* __restrict__ dst) {
    int e = blockIdx.x * blockDim.x + threadIdx.x;
    if (e < EE) atomicAdd(&g_cnt[dst[e]], 1);
}

// Fused scan + finalize + prescale (98 co-resident blocks).
__global__ void __launch_bounds__(1024, 1) k_scanfin(const float* __restrict__ x) {
    __shared__ int sh[1024];
    __shared__ int bs[NBLK];
    int tid = threadIdx.x;
    int b = blockIdx.x;
    int i = b * 1024 + tid;
    int c = (i < NN) ? g_cnt[i] : 0;
    sh[tid] = c;
    __syncthreads();
#pragma unroll
    for (int off = 1; off < 1024; off <<= 1) {
        int t = (tid >= off) ? sh[tid - off] : 0;
        __syncthreads();
        sh[tid] += t;
        __syncthreads();
    }
    int excl = sh[tid] - c;

    if (tid == 0) {
        ((volatile int*)g_blocksum)[b] = sh[1023] + 1;
        __threadfence();
    }
    // zero the dummy rows (any one block; do it while others scan)
    if (b == 0) {
        __half2 z2 = __floats2half2_rn(0.f, 0.f);
        if (tid >= 32 && tid < 40)  ((__half2*)g_hx)[NN * 8 + (tid - 32)] = z2;
        if (tid >= 40 && tid < 56)  ((__half2*)g_h1)[NN * 16 + (tid - 40)] = z2;
        if (tid >= 56 && tid < 64)  ((__half2*)g_h2)[NN * 8 + (tid - 56)] = z2;
    }
    if (tid < NBLK) {
        volatile int* vb = (volatile int*)g_blocksum;
        int v;
        do { v = vb[tid]; } while (v == 0);
        bs[tid] = v - 1;
    }
    __syncthreads();
    if (tid < 32) {
        int lane = tid;
        int acc = 0;
        for (int base = 0; base < NBLK; base += 32) {
            int j = base + lane;
            int orig = (j < NBLK) ? bs[j] : 0;
            int v = orig;
#pragma unroll
            for (int off = 1; off < 32; off <<= 1) {
                int t = __shfl_up_sync(0xffffffffu, v, off);
                if (lane >= off) v += t;
            }
            int ex = acc + v - orig;
            acc += __shfl_sync(0xffffffffu, v, 31);
            __syncwarp();
            if (j < NBLK) bs[j] = ex;
        }
    }
    __syncthreads();

    if (i >= NN) return;
    int r = excl + bs[b];
    g_rowptr[i] = r;
    g_cur[i] = r;
    float d = rsqrtf((float)c + 1.0f);
    g_dis[i] = d;
    if (i == 0) g_rowptr[NN] = EE;
    __half2* o = ((__half2*)g_hx) + i * 8;
#pragma unroll
    for (int j = 0; j < 8; j++) {
        float a = x[i * 16 + 2 * j] * d;
        float bb = x[i * 16 + 2 * j + 1] * d;
        o[j] = __floats2half2_rn(a, bb);
    }
}

__global__ void k_scatter(const int* __restrict__ src, const int* __restrict__ dst) {
    int e = blockIdx.x * blockDim.x + threadIdx.x;
    if (e >= EE) return;
    int pos = atomicAdd(&g_cur[dst[e]], 1);
    g_csr_src[pos] = src[e];
}

// ---------------- helpers ----------------
__device__ __forceinline__ void acc_u2(uint2 u, float& a0, float& a1, float& a2, float& a3) {
    float2 f0 = __half22float2(*reinterpret_cast<__half2*>(&u.x));
    float2 f1 = __half22float2(*reinterpret_cast<__half2*>(&u.y));
    a0 += f0.x; a1 += f0.y; a2 += f1.x; a3 += f1.y;
}

// ---------------- aggregation ----------------
// D=16 rows = 4 uint2 (32B). 4 lanes/row (r=lane&3), 8 edge slots (g=lane>>3... g=lane>>2).
// One row-LDG instruction covers 8 edges. Bulk loop: no bounds checks; tail uses dummy row NN.
// MODE 0: y fp16 | MODE 1: softmax -> fp16 dis-scaled | MODE 2: softmax -> fp32
template <int MODE>
__global__ void k_agg16h(const __half* __restrict__ xin, void* __restrict__ yout,
                         const float* __restrict__ bsm) {
    int warp = (blockIdx.x * blockDim.x + threadIdx.x) >> 5;
    if (warp >= NN) return;
    int lane = threadIdx.x & 31;
    int r = lane & 3;            // uint2 slot within row (features 4r..4r+3)
    int g = lane >> 2;           // edge slot 0..7
    int beg = __ldg(&g_rowptr[warp]);
    int end = __ldg(&g_rowptr[warp + 1]);
    const uint2* __restrict__ x2 = (const uint2*)xin;

    float a0 = 0.f, a1 = 0.f, a2 = 0.f, a3 = 0.f;
    if (g == 0) acc_u2(x2[warp * 4 + r], a0, a1, a2, a3);   // self loop

    int e = beg;
    // 2-wide bulk: 16 edges in flight
    for (; e + 16 <= end; e += 16) {
        int sa = __ldg(&g_csr_src[e + g]);
        int sb = __ldg(&g_csr_src[e + 8 + g]);
        uint2 ua = x2[sa * 4 + r];
        uint2 ub = x2[sb * 4 + r];
        acc_u2(ua, a0, a1, a2, a3);
        acc_u2(ub, a0, a1, a2, a3);
    }
    if (e + 8 <= end) {
        int s = __ldg(&g_csr_src[e + g]);
        acc_u2(x2[s * 4 + r], a0, a1, a2, a3);
        e += 8;
    }
    // tail (<8 edges): clamp to dummy zero row
    if (e < end) {
        int s = (e + g < end) ? __ldg(&g_csr_src[e + g]) : NN;
        acc_u2(x2[s * 4 + r], a0, a1, a2, a3);
    }

    // reduce across the 8 edge slots (stride 4, 8, 16)
#pragma unroll
    for (int m = 4; m <= 16; m <<= 1) {
        a0 += __shfl_xor_sync(0xffffffffu, a0, m);
        a1 += __shfl_xor_sync(0xffffffffu, a1, m);
        a2 += __shfl_xor_sync(0xffffffffu, a2, m);
        a3 += __shfl_xor_sync(0xffffffffu, a3, m);
    }

    float d = g_dis[warp];
    a0 *= d; a1 *= d; a2 *= d; a3 *= d;

    if (MODE == 0) {
        if (lane < 4) {
            uint2 u;
            *reinterpret_cast<__half2*>(&u.x) = __floats2half2_rn(a0, a1);
            *reinterpret_cast<__half2*>(&u.y) = __floats2half2_rn(a2, a3);
            ((uint2*)yout)[warp * 4 + r] = u;
        }
        return;
    }
    a0 += bsm[4 * r + 0]; a1 += bsm[4 * r + 1];
    a2 += bsm[4 * r + 2]; a3 += bsm[4 * r + 3];
    float m = fmaxf(fmaxf(a0, a1), fmaxf(a2, a3));
    m = fmaxf(m, __shfl_xor_sync(0xffffffffu, m, 1));
    m = fmaxf(m, __shfl_xor_sync(0xffffffffu, m, 2));
    a0 = __expf(a0 - m); a1 = __expf(a1 - m);
    a2 = __expf(a2 - m); a3 = __expf(a3 - m);
    float s = a0 + a1 + a2 + a3;
    s += __shfl_xor_sync(0xffffffffu, s, 1);
    s += __shfl_xor_sync(0xffffffffu, s, 2);
    float inv = 1.0f / s;
    a0 *= inv; a1 *= inv; a2 *= inv; a3 *= inv;

    if (MODE == 1) {
        if (lane < 4) {
            uint2 u;
            *reinterpret_cast<__half2*>(&u.x) = __floats2half2_rn(a0 * d, a1 * d);
            *reinterpret_cast<__half2*>(&u.y) = __floats2half2_rn(a2 * d, a3 * d);
            ((uint2*)yout)[warp * 4 + r] = u;
        }
    } else {
        if (lane < 4)
            ((float4*)yout)[warp * 4 + r] = make_float4(a0, a1, a2, a3);
    }
}

// D=32 rows = 8 uint2 (64B). 8 lanes/row (r=lane&7), 4 edge slots (g=lane>>3).
__global__ void k_agg32h(const __half* __restrict__ xin, __half* __restrict__ yout) {
    int warp = (blockIdx.x * blockDim.x + threadIdx.x) >> 5;
    if (warp >= NN) return;
    int lane = threadIdx.x & 31;
    int r = lane & 7;            // uint2 slot (features 4r..4r+3)
    int g = lane >> 3;           // edge slot 0..3
    int beg = __ldg(&g_rowptr[warp]);
    int end = __ldg(&g_rowptr[warp + 1]);
    const uint2* __restrict__ x2 = (const uint2*)xin;

    float a0 = 0.f, a1 = 0.f, a2 = 0.f, a3 = 0.f;
    if (g == 0) acc_u2(x2[warp * 8 + r], a0, a1, a2, a3);

    int e = beg;
    // 2-wide bulk: 8 edges in flight
    for (; e + 8 <= end; e += 8) {
        int sa = __ldg(&g_csr_src[e + g]);
        int sb = __ldg(&g_csr_src[e + 4 + g]);
        uint2 ua = x2[sa * 8 + r];
        uint2 ub = x2[sb * 8 + r];
        acc_u2(ua, a0, a1, a2, a3);
        acc_u2(ub, a0, a1, a2, a3);
    }
    if (e + 4 <= end) {
        int s = __ldg(&g_csr_src[e + g]);
        acc_u2(x2[s * 8 + r], a0, a1, a2, a3);
        e += 4;
    }
    if (e < end) {
        int s = (e + g < end) ? __ldg(&g_csr_src[e + g]) : NN;
        acc_u2(x2[s * 8 + r], a0, a1, a2, a3);
    }

#pragma unroll
    for (int m = 8; m <= 16; m <<= 1) {
        a0 += __shfl_xor_sync(0xffffffffu, a0, m);
        a1 += __shfl_xor_sync(0xffffffffu, a1, m);
        a2 += __shfl_xor_sync(0xffffffffu, a2, m);
        a3 += __shfl_xor_sync(0xffffffffu, a3, m);
    }

    float d = g_dis[warp];
    if (lane < 8) {
        uint2 u;
        *reinterpret_cast<__half2*>(&u.x) = __floats2half2_rn(a0 * d, a1 * d);
        *reinterpret_cast<__half2*>(&u.y) = __floats2half2_rn(a2 * d, a3 * d);
        ((uint2*)yout)[warp * 8 + r] = u;
    }
}

// ---------------- fused per-node GEMM: z~ = dis * (relu(y@W1 + b1) @ W2) ----------------
__global__ void k_gemm_fused(const __half* __restrict__ yin, __half* __restrict__ zout,
                             const float* __restrict__ W1, const float* __restrict__ b1,
                             const float* __restrict__ W2) {
    __shared__ float W1t[64 * 16];   // [k][m]
    __shared__ float W2s[64 * 32];   // [k][j]
    __shared__ float b1s[64];
    for (int t = threadIdx.x; t < 16 * 64; t += blockDim.x) {
        int m = t >> 6, k = t & 63;          // W1 is [m][k]
        W1t[k * 16 + m] = W1[t];
    }
    for (int t = threadIdx.x; t < 64 * 32; t += blockDim.x) W2s[t] = W2[t];
    for (int t = threadIdx.x; t < 64; t += blockDim.x) b1s[t] = b1[t];
    __syncthreads();

    int i = blockIdx.x * blockDim.x + threadIdx.x;
    if (i >= NN) return;

    float xr[16];
    {
        const uint4* yv = (const uint4*)yin;
        uint4 q0 = yv[i * 2 + 0];
        uint4 q1 = yv[i * 2 + 1];
        const unsigned* w0 = (const unsigned*)&q0;
        const unsigned* w1 = (const unsigned*)&q1;
#pragma unroll
        for (int j = 0; j < 4; j++) {
            float2 f = __half22float2(*reinterpret_cast<const __half2*>(&w0[j]));
            xr[2 * j] = f.x; xr[2 * j + 1] = f.y;
            float2 g2 = __half22float2(*reinterpret_cast<const __half2*>(&w1[j]));
            xr[8 + 2 * j] = g2.x; xr[8 + 2 * j + 1] = g2.y;
        }
    }
    float4 z4[8];
#pragma unroll
    for (int j = 0; j < 8; j++) z4[j] = make_float4(0.f, 0.f, 0.f, 0.f);

    const float4* W1t4 = (const float4*)W1t;
    const float4* W2s4 = (const float4*)W2s;
#pragma unroll 4
    for (int k = 0; k < 64; k++) {
        float t = b1s[k];
#pragma unroll
        for (int q = 0; q < 4; q++) {
            float4 w = W1t4[k * 4 + q];
            t += xr[4 * q + 0] * w.x + xr[4 * q + 1] * w.y
               + xr[4 * q + 2] * w.z + xr[4 * q + 3] * w.w;
        }
        t = fmaxf(t, 0.0f);
#pragma unroll
        for (int j = 0; j < 8; j++) {
            float4 w = W2s4[k * 8 + j];
            z4[j].x += t * w.x; z4[j].y += t * w.y;
            z4[j].z += t * w.z; z4[j].w += t * w.w;
        }
    }

    float d = g_dis[i];
    __half2* o = ((__half2*)zout) + i * 16;
#pragma unroll
    for (int j = 0; j < 8; j++) {
        o[2 * j + 0] = __floats2half2_rn(z4[j].x * d, z4[j].y * d);
        o[2 * j + 1] = __floats2half2_rn(z4[j].z * d, z4[j].w * d);
    }
}

// ---------------- gemm3: h~ = dis * (relu(z + b2) @ W3) ----------------
__global__ void k_gemm3(const __half* __restrict__ zin, __half* __restrict__ hout,
                        const float* __restrict__ b2, const float* __restrict__ W3) {
    __shared__ float W3s[32 * 16];
    __shared__ float b2s[32];
    for (int t = threadIdx.x; t < 32 * 16; t += blockDim.x) W3s[t] = W3[t];
    for (int t = threadIdx.x; t < 32; t += blockDim.x) b2s[t] = b2[t];
    __syncthreads();

    int i = blockIdx.x * blockDim.x + threadIdx.x;
    if (i >= NN) return;

    float4 acc[4];
#pragma unroll
    for (int j = 0; j < 4; j++) acc[j] = make_float4(0.f, 0.f, 0.f, 0.f);

    const float4* W3s4 = (const float4*)W3s;
    const uint4* zv = (const uint4*)zin;
#pragma unroll
    for (int m = 0; m < 4; m++) {
        uint4 q = zv[i * 4 + m];
        const unsigned* w = (const unsigned*)&q;
#pragma unroll
        for (int p = 0; p < 4; p++) {
            float2 f = __half22float2(*reinterpret_cast<const __half2*>(&w[p]));
            int k0 = m * 8 + 2 * p;
            float t0 = fmaxf(f.x + b2s[k0], 0.0f);
            float t1 = fmaxf(f.y + b2s[k0 + 1], 0.0f);
#pragma unroll
            for (int j = 0; j < 4; j++) {
                float4 wa = W3s4[k0 * 4 + j];
                float4 wb = W3s4[(k0 + 1) * 4 + j];
                acc[j].x += t0 * wa.x + t1 * wb.x;
                acc[j].y += t0 * wa.y + t1 * wb.y;
                acc[j].z += t0 * wa.z + t1 * wb.z;
                acc[j].w += t0 * wa.w + t1 * wb.w;
            }
        }
    }

    float d = g_dis[i];
    __half2* o = ((__half2*)hout) + i * 8;
#pragma unroll
    for (int j = 0; j < 4; j++) {
        o[2 * j + 0] = __floats2half2_rn(acc[j].x * d, acc[j].y * d);
        o[2 * j + 1] = __floats2half2_rn(acc[j].z * d, acc[j].w * d);
    }
}

// ---------------- launch ----------------
extern "C" void kernel_launch(void* const* d_in, const int* in_sizes, int n_in,
                              void* d_out, int out_size) {
    const float* x  = (const float*)d_in[0];
    const int*   ei = (const int*)d_in[1];
    const int*   src = ei;
    const int*   dst = ei + EE;
    const float* W1 = (const float*)d_in[2];
    const float* b1 = (const float*)d_in[3];
    const float* W2 = (const float*)d_in[4];
    const float* b2 = (const float*)d_in[5];
    const float* W3 = (const float*)d_in[6];
    const float* b3 = (const float*)d_in[7];
    float* out = (float*)d_out;

    __half *pHX, *pHY, *pH1, *pHZ, *pH2;
    int *pCnt, *pBS;
    cudaGetSymbolAddress((void**)&pHX, g_hx);
    cudaGetSymbolAddress((void**)&pHY, g_hy);
    cudaGetSymbolAddress((void**)&pH1, g_h1);
    cudaGetSymbolAddress((void**)&pHZ, g_hz);
    cudaGetSymbolAddress((void**)&pH2, g_h2);
    cudaGetSymbolAddress((void**)&pCnt, g_cnt);
    cudaGetSymbolAddress((void**)&pBS, g_blocksum);

    const int TB = 256;
    const int gE = (EE + TB - 1) / TB;
    const int gW = (NN * 32 + TB - 1) / TB;   // warp-per-node
    const int gG = (NN + 127) / 128;

    // CSR build: hist(1), scanfin(2), scatter(3) -> first agg16 is 4th kernel (ncu target)
    cudaMemsetAsync(pCnt, 0, NN * sizeof(int));
    cudaMemsetAsync(pBS, 0, NBLK * sizeof(int));
    k_hist<<<gE, TB>>>(dst);
    k_scanfin<<<NBLK, 1024>>>(x);
    k_scatter<<<gE, TB>>>(src, dst);

    for (int blk = 0; blk < 5; blk++) {
        k_agg16h<0><<<gW, TB>>>(pHX, pHY, nullptr);
        k_gemm_fused<<<gG, 128>>>(pHY, pH1, W1 + blk * 16 * 64, b1 + blk * 64,
                                  W2 + blk * 64 * 32);
        k_agg32h<<<gW, TB>>>(pH1, pHZ);
        k_gemm3<<<gG, 128>>>(pHZ, pH2, b2 + blk * 32, W3 + blk * 32 * 16);
        if (blk == 4)
            k_agg16h<2><<<gW, TB>>>(pH2, out, b3 + blk * 16);
        else
            k_agg16h<1><<<gW, TB>>>(pH2, pHX, b3 + blk * 16);
    }
}

// round 11
// speedup vs baseline: 1.0960x; 1.0041x over previous
#include <cuda_runtime.h>
#include <cuda_fp16.h>

#define NN 100000
#define EE 3200000
#define NBLK ((NN + 1023) / 1024)   // 98 scan blocks (all co-resident)

// ---- scratch (device globals; no allocation allowed) ----
__device__ int    g_cnt[NN];
__device__ int    g_blocksum[NBLK];    // published totals+1 (memset 0 per replay)
__device__ int    g_rowptr[NN + 1];
__device__ int    g_cur[NN];
__device__ int    g_csr_src[EE];
__device__ float  g_dis[NN];            // rsqrt(deg)
// gathered arrays have a dummy zero row at index NN
__device__ __half g_hx[(NN + 1) * 16];  // x~ block input (dis-scaled fp16)
__device__ __half g_hy[NN * 16];        // y  = agg16 out (fp16)
__device__ __half g_h1[(NN + 1) * 32];  // z~ = gemm_fused out (dis-scaled fp16)
__device__ __half g_hz[NN * 32];        // z  = agg32 out (fp16)
__device__ __half g_h2[(NN + 1) * 16];  // h~ = gemm3 out (dis-scaled fp16)

// ---------------- packed f32x2 helpers ----------------
__device__ __forceinline__ unsigned long long ffma2(unsigned long long a,
                                                    unsigned long long b,
                                                    unsigned long long c) {
    unsigned long long d;
    asm("fma.rn.f32x2 %0, %1, %2, %3;" : "=l"(d) : "l"(a), "l"(b), "l"(c));
    return d;
}
__device__ __forceinline__ unsigned long long pack2(float x, float y) {
    unsigned long long r;
    asm("mov.b64 %0, {%1, %2};" : "=l"(r) : "f"(x), "f"(y));
    return r;
}
__device__ __forceinline__ float2 unpack2(unsigned long long v) {
    float x, y;
    asm("mov.b64 {%0, %1}, %2;" : "=f"(x), "=f"(y) : "l"(v));
    return make_float2(x, y);
}

// ---------------- CSR build ----------------
__global__ void k_hist(const int* __restrict__ dst) {
    int e = blockIdx.x * blockDim.x + threadIdx.x;
    if (e < EE) atomicAdd(&g_cnt[dst[e]], 1);
}

// Fused scan + finalize + prescale (98 co-resident blocks).
__global__ void __launch_bounds__(1024, 1) k_scanfin(const float* __restrict__ x) {
    __shared__ int sh[1024];
    __shared__ int bs[NBLK];
    int tid = threadIdx.x;
    int b = blockIdx.x;
    int i = b * 1024 + tid;
    int c = (i < NN) ? g_cnt[i] : 0;
    sh[tid] = c;
    __syncthreads();
#pragma unroll
    for (int off = 1; off < 1024; off <<= 1) {
        int t = (tid >= off) ? sh[tid - off] : 0;
        __syncthreads();
        sh[tid] += t;
        __syncthreads();
    }
    int excl = sh[tid] - c;

    if (tid == 0) {
        ((volatile int*)g_blocksum)[b] = sh[1023] + 1;
        __threadfence();
    }
    // zero the dummy rows (block 0, spare lanes)
    if (b == 0) {
        __half2 z2 = __floats2half2_rn(0.f, 0.f);
        if (tid >= 32 && tid < 40)  ((__half2*)g_hx)[NN * 8 + (tid - 32)] = z2;
        if (tid >= 40 && tid < 56)  ((__half2*)g_h1)[NN * 16 + (tid - 40)] = z2;
        if (tid >= 56 && tid < 64)  ((__half2*)g_h2)[NN * 8 + (tid - 56)] = z2;
    }
    if (tid < NBLK) {
        volatile int* vb = (volatile int*)g_blocksum;
        int v;
        do { v = vb[tid]; } while (v == 0);
        bs[tid] = v - 1;
    }
    __syncthreads();
    if (tid < 32) {
        int lane = tid;
        int acc = 0;
        for (int base = 0; base < NBLK; base += 32) {
            int j = base + lane;
            int orig = (j < NBLK) ? bs[j] : 0;
            int v = orig;
#pragma unroll
            for (int off = 1; off < 32; off <<= 1) {
                int t = __shfl_up_sync(0xffffffffu, v, off);
                if (lane >= off) v += t;
            }
            int ex = acc + v - orig;
            acc += __shfl_sync(0xffffffffu, v, 31);
            __syncwarp();
            if (j < NBLK) bs[j] = ex;
        }
    }
    __syncthreads();

    if (i >= NN) return;
    int r = excl + bs[b];
    g_rowptr[i] = r;
    g_cur[i] = r;
    float d = rsqrtf((float)c + 1.0f);
    g_dis[i] = d;
    if (i == 0) g_rowptr[NN] = EE;
    __half2* o = ((__half2*)g_hx) + i * 8;
#pragma unroll
    for (int j = 0; j < 8; j++) {
        float a = x[i * 16 + 2 * j] * d;
        float bb = x[i * 16 + 2 * j + 1] * d;
        o[j] = __floats2half2_rn(a, bb);
    }
}

__global__ void k_scatter(const int* __restrict__ src, const int* __restrict__ dst) {
    int e = blockIdx.x * blockDim.x + threadIdx.x;
    if (e >= EE) return;
    int pos = atomicAdd(&g_cur[dst[e]], 1);
    g_csr_src[pos] = src[e];
}

// ---------------- helpers ----------------
__device__ __forceinline__ void acc_u2(uint2 u, float& a0, float& a1, float& a2, float& a3) {
    float2 f0 = __half22float2(*reinterpret_cast<__half2*>(&u.x));
    float2 f1 = __half22float2(*reinterpret_cast<__half2*>(&u.y));
    a0 += f0.x; a1 += f0.y; a2 += f1.x; a3 += f1.y;
}

// ---------------- aggregation ----------------
// D=16 rows = 4 uint2 (32B). 4 lanes/row, 8 edge slots; dummy row NN for tails.
// MODE 0: y fp16 | MODE 1: softmax -> fp16 dis-scaled | MODE 2: softmax -> fp32
template <int MODE>
__global__ void k_agg16h(const __half* __restrict__ xin, void* __restrict__ yout,
                         const float* __restrict__ bsm) {
    int warp = (blockIdx.x * blockDim.x + threadIdx.x) >> 5;
    if (warp >= NN) return;
    int lane = threadIdx.x & 31;
    int r = lane & 3;
    int g = lane >> 2;           // edge slot 0..7
    int beg = __ldg(&g_rowptr[warp]);
    int end = __ldg(&g_rowptr[warp + 1]);
    const uint2* __restrict__ x2 = (const uint2*)xin;

    float a0 = 0.f, a1 = 0.f, a2 = 0.f, a3 = 0.f;
    if (g == 0) acc_u2(x2[warp * 4 + r], a0, a1, a2, a3);   // self loop

    int e = beg;
    for (; e + 16 <= end; e += 16) {
        int sa = __ldg(&g_csr_src[e + g]);
        int sb = __ldg(&g_csr_src[e + 8 + g]);
        uint2 ua = x2[sa * 4 + r];
        uint2 ub = x2[sb * 4 + r];
        acc_u2(ua, a0, a1, a2, a3);
        acc_u2(ub, a0, a1, a2, a3);
    }
    if (e + 8 <= end) {
        int s = __ldg(&g_csr_src[e + g]);
        acc_u2(x2[s * 4 + r], a0, a1, a2, a3);
        e += 8;
    }
    if (e < end) {
        int s = (e + g < end) ? __ldg(&g_csr_src[e + g]) : NN;
        acc_u2(x2[s * 4 + r], a0, a1, a2, a3);
    }

#pragma unroll
    for (int m = 4; m <= 16; m <<= 1) {
        a0 += __shfl_xor_sync(0xffffffffu, a0, m);
        a1 += __shfl_xor_sync(0xffffffffu, a1, m);
        a2 += __shfl_xor_sync(0xffffffffu, a2, m);
        a3 += __shfl_xor_sync(0xffffffffu, a3, m);
    }

    float d = g_dis[warp];
    a0 *= d; a1 *= d; a2 *= d; a3 *= d;

    if (MODE == 0) {
        if (lane < 4) {
            uint2 u;
            *reinterpret_cast<__half2*>(&u.x) = __floats2half2_rn(a0, a1);
            *reinterpret_cast<__half2*>(&u.y) = __floats2half2_rn(a2, a3);
            ((uint2*)yout)[warp * 4 + r] = u;
        }
        return;
    }
    a0 += bsm[4 * r + 0]; a1 += bsm[4 * r + 1];
    a2 += bsm[4 * r + 2]; a3 += bsm[4 * r + 3];
    float m = fmaxf(fmaxf(a0, a1), fmaxf(a2, a3));
    m = fmaxf(m, __shfl_xor_sync(0xffffffffu, m, 1));
    m = fmaxf(m, __shfl_xor_sync(0xffffffffu, m, 2));
    a0 = __expf(a0 - m); a1 = __expf(a1 - m);
    a2 = __expf(a2 - m); a3 = __expf(a3 - m);
    float s = a0 + a1 + a2 + a3;
    s += __shfl_xor_sync(0xffffffffu, s, 1);
    s += __shfl_xor_sync(0xffffffffu, s, 2);
    float inv = 1.0f / s;
    a0 *= inv; a1 *= inv; a2 *= inv; a3 *= inv;

    if (MODE == 1) {
        if (lane < 4) {
            uint2 u;
            *reinterpret_cast<__half2*>(&u.x) = __floats2half2_rn(a0 * d, a1 * d);
            *reinterpret_cast<__half2*>(&u.y) = __floats2half2_rn(a2 * d, a3 * d);
            ((uint2*)yout)[warp * 4 + r] = u;
        }
    } else {
        if (lane < 4)
            ((float4*)yout)[warp * 4 + r] = make_float4(a0, a1, a2, a3);
    }
}

// D=32 rows = 8 uint2 (64B). 8 lanes/row, 4 edge slots.
__global__ void k_agg32h(const __half* __restrict__ xin, __half* __restrict__ yout) {
    int warp = (blockIdx.x * blockDim.x + threadIdx.x) >> 5;
    if (warp >= NN) return;
    int lane = threadIdx.x & 31;
    int r = lane & 7;
    int g = lane >> 3;           // edge slot 0..3
    int beg = __ldg(&g_rowptr[warp]);
    int end = __ldg(&g_rowptr[warp + 1]);
    const uint2* __restrict__ x2 = (const uint2*)xin;

    float a0 = 0.f, a1 = 0.f, a2 = 0.f, a3 = 0.f;
    if (g == 0) acc_u2(x2[warp * 8 + r], a0, a1, a2, a3);

    int e = beg;
    for (; e + 8 <= end; e += 8) {
        int sa = __ldg(&g_csr_src[e + g]);
        int sb = __ldg(&g_csr_src[e + 4 + g]);
        uint2 ua = x2[sa * 8 + r];
        uint2 ub = x2[sb * 8 + r];
        acc_u2(ua, a0, a1, a2, a3);
        acc_u2(ub, a0, a1, a2, a3);
    }
    if (e + 4 <= end) {
        int s = __ldg(&g_csr_src[e + g]);
        acc_u2(x2[s * 8 + r], a0, a1, a2, a3);
        e += 4;
    }
    if (e < end) {
        int s = (e + g < end) ? __ldg(&g_csr_src[e + g]) : NN;
        acc_u2(x2[s * 8 + r], a0, a1, a2, a3);
    }

#pragma unroll
    for (int m = 8; m <= 16; m <<= 1) {
        a0 += __shfl_xor_sync(0xffffffffu, a0, m);
        a1 += __shfl_xor_sync(0xffffffffu, a1, m);
        a2 += __shfl_xor_sync(0xffffffffu, a2, m);
        a3 += __shfl_xor_sync(0xffffffffu, a3, m);
    }

    float d = g_dis[warp];
    if (lane < 8) {
        uint2 u;
        *reinterpret_cast<__half2*>(&u.x) = __floats2half2_rn(a0 * d, a1 * d);
        *reinterpret_cast<__half2*>(&u.y) = __floats2half2_rn(a2 * d, a3 * d);
        ((uint2*)yout)[warp * 8 + r] = u;
    }
}

// ---------------- fused per-node GEMM: z~ = dis * (relu(y@W1 + b1) @ W2) ----------------
// f32x2 packed math: 24 FFMA2 per k instead of 48 FFMA.
__global__ void k_gemm_fused(const __half* __restrict__ yin, __half* __restrict__ zout,
                             const float* __restrict__ W1, const float* __restrict__ b1,
                             const float* __restrict__ W2) {
    __shared__ float W1t[64 * 16];   // [k][m]
    __shared__ float W2s[64 * 32];   // [k][j]
    __shared__ float b1s[64];
    for (int t = threadIdx.x; t < 16 * 64; t += blockDim.x) {
        int m = t >> 6, k = t & 63;          // W1 is [m][k]
        W1t[k * 16 + m] = W1[t];
    }
    for (int t = threadIdx.x; t < 64 * 32; t += blockDim.x) W2s[t] = W2[t];
    for (int t = threadIdx.x; t < 64; t += blockDim.x) b1s[t] = b1[t];
    __syncthreads();

    int i = blockIdx.x * blockDim.x + threadIdx.x;
    if (i >= NN) return;

    // load y row (fp16) -> 8 packed f32 pairs
    unsigned long long xr2[8];
    {
        const uint4* yv = (const uint4*)yin;
        uint4 q0 = yv[i * 2 + 0];
        uint4 q1 = yv[i * 2 + 1];
        const unsigned* w0 = (const unsigned*)&q0;
        const unsigned* w1 = (const unsigned*)&q1;
#pragma unroll
        for (int j = 0; j < 4; j++) {
            float2 f = __half22float2(*reinterpret_cast<const __half2*>(&w0[j]));
            xr2[j] = pack2(f.x, f.y);
            float2 g2 = __half22float2(*reinterpret_cast<const __half2*>(&w1[j]));
            xr2[4 + j] = pack2(g2.x, g2.y);
        }
    }
    unsigned long long z2[16];
#pragma unroll
    for (int j = 0; j < 16; j++) z2[j] = 0ull;

    const ulonglong2* W1p = (const ulonglong2*)W1t;   // row k = 4 ulonglong2
    const ulonglong2* W2p = (const ulonglong2*)W2s;   // row k = 8 ulonglong2
#pragma unroll 4
    for (int k = 0; k < 64; k++) {
        unsigned long long t2 = 0ull;
#pragma unroll
        for (int q = 0; q < 4; q++) {
            ulonglong2 w = W1p[k * 4 + q];
            t2 = ffma2(xr2[2 * q + 0], w.x, t2);
            t2 = ffma2(xr2[2 * q + 1], w.y, t2);
        }
        float2 tt = unpack2(t2);
        float t = fmaxf(tt.x + tt.y + b1s[k], 0.0f);
        unsigned long long td = pack2(t, t);
#pragma unroll
        for (int j = 0; j < 8; j++) {
            ulonglong2 w = W2p[k * 8 + j];
            z2[2 * j + 0] = ffma2(td, w.x, z2[2 * j + 0]);
            z2[2 * j + 1] = ffma2(td, w.y, z2[2 * j + 1]);
        }
    }

    float d = g_dis[i];
    __half2* o = ((__half2*)zout) + i * 16;
#pragma unroll
    for (int p = 0; p < 16; p++) {
        float2 f = unpack2(z2[p]);
        o[p] = __floats2half2_rn(f.x * d, f.y * d);
    }
}

// ---------------- gemm3: h~ = dis * (relu(z + b2) @ W3), f32x2 packed ----------------
__global__ void k_gemm3(const __half* __restrict__ zin, __half* __restrict__ hout,
                        const float* __restrict__ b2, const float* __restrict__ W3) {
    __shared__ float W3s[32 * 16];   // [k][j]
    __shared__ float b2s[32];
    for (int t = threadIdx.x; t < 32 * 16; t += blockDim.x) W3s[t] = W3[t];
    for (int t = threadIdx.x; t < 32; t += blockDim.x) b2s[t] = b2[t];
    __syncthreads();

    int i = blockIdx.x * blockDim.x + threadIdx.x;
    if (i >= NN) return;

    unsigned long long acc2[8];
#pragma unroll
    for (int j = 0; j < 8; j++) acc2[j] = 0ull;

    const ulonglong2* W3p = (const ulonglong2*)W3s;   // row k = 4 ulonglong2
    const uint4* zv = (const uint4*)zin;
#pragma unroll
    for (int m = 0; m < 4; m++) {
        uint4 q = zv[i * 4 + m];
        const unsigned* w = (const unsigned*)&q;
#pragma unroll
        for (int p = 0; p < 4; p++) {
            float2 f = __half22float2(*reinterpret_cast<const __half2*>(&w[p]));
            int k0 = m * 8 + 2 * p;
            float t0 = fmaxf(f.x + b2s[k0], 0.0f);
            float t1 = fmaxf(f.y + b2s[k0 + 1], 0.0f);
            unsigned long long t02 = pack2(t0, t0);
            unsigned long long t12 = pack2(t1, t1);
#pragma unroll
            for (int jj = 0; jj < 4; jj++) {
                ulonglong2 wa = W3p[k0 * 4 + jj];
                ulonglong2 wb = W3p[(k0 + 1) * 4 + jj];
                acc2[2 * jj + 0] = ffma2(t02, wa.x, acc2[2 * jj + 0]);
                acc2[2 * jj + 1] = ffma2(t02, wa.y, acc2[2 * jj + 1]);
                acc2[2 * jj + 0] = ffma2(t12, wb.x, acc2[2 * jj + 0]);
                acc2[2 * jj + 1] = ffma2(t12, wb.y, acc2[2 * jj + 1]);
            }
        }
    }

    float d = g_dis[i];
    __half2* o = ((__half2*)hout) + i * 8;
#pragma unroll
    for (int p = 0; p < 8; p++) {
        float2 f = unpack2(acc2[p]);
        o[p] = __floats2half2_rn(f.x * d, f.y * d);
    }
}

// ---------------- launch ----------------
extern "C" void kernel_launch(void* const* d_in, const int* in_sizes, int n_in,
                              void* d_out, int out_size) {
    const float* x  = (const float*)d_in[0];
    const int*   ei = (const int*)d_in[1];
    const int*   src = ei;
    const int*   dst = ei + EE;
    const float* W1 = (const float*)d_in[2];
    const float* b1 = (const float*)d_in[3];
    const float* W2 = (const float*)d_in[4];
    const float* b2 = (const float*)d_in[5];
    const float* W3 = (const float*)d_in[6];
    const float* b3 = (const float*)d_in[7];
    float* out = (float*)d_out;

    __half *pHX, *pHY, *pH1, *pHZ, *pH2;
    int *pCnt, *pBS;
    cudaGetSymbolAddress((void**)&pHX, g_hx);
    cudaGetSymbolAddress((void**)&pHY, g_hy);
    cudaGetSymbolAddress((void**)&pH1, g_h1);
    cudaGetSymbolAddress((void**)&pHZ, g_hz);
    cudaGetSymbolAddress((void**)&pH2, g_h2);
    cudaGetSymbolAddress((void**)&pCnt, g_cnt);
    cudaGetSymbolAddress((void**)&pBS, g_blocksum);

    const int TB = 256;
    const int gE = (EE + TB - 1) / TB;
    const int gW = (NN * 32 + TB - 1) / TB;   // warp-per-node
    const int gG = (NN + 127) / 128;

    // CSR build: hist(1), scanfin(2), scatter(3) -> first agg16 is 4th kernel (ncu target)
    cudaMemsetAsync(pCnt, 0, NN * sizeof(int));
    cudaMemsetAsync(pBS, 0, NBLK * sizeof(int));
    k_hist<<<gE, TB>>>(dst);
    k_scanfin<<<NBLK, 1024>>>(x);
    k_scatter<<<gE, TB>>>(src, dst);

    for (int blk = 0; blk < 5; blk++) {
        k_agg16h<0><<<gW, TB>>>(pHX, pHY, nullptr);
        k_gemm_fused<<<gG, 128>>>(pHY, pH1, W1 + blk * 16 * 64, b1 + blk * 64,
                                  W2 + blk * 64 * 32);
        k_agg32h<<<gW, TB>>>(pH1, pHZ);
        k_gemm3<<<gG, 128>>>(pHZ, pH2, b2 + blk * 32, W3 + blk * 32 * 16);
        if (blk == 4)
            k_agg16h<2><<<gW, TB>>>(pH2, out, b3 + blk * 16);
        else
            k_agg16h<1><<<gW, TB>>>(pH2, pHX, b3 + blk * 16);
    }
}